// round 15
// baseline (speedup 1.0000x reference)
#include <cuda_runtime.h>
#include <cuda_fp16.h>
#include <math.h>
#include <stdint.h>

#define Nn 8192
#define Mm 2048
#define Dd 768
#define EPS_D 0.0025
#define L2E 1.4426950408889634f
#define LN2 0.6931471805599453
#define SCL (400.0f * L2E)   // cost scale in log2 units

static __device__ __align__(16) __half g_dh[(size_t)Nn * Dd];
static __device__ __align__(16) __half g_sih[(size_t)Mm * Dd];
static __device__ __align__(16) __half g_Wh[(size_t)Dd * Dd];
static __device__ __align__(16) __half g_Xh[(size_t)Nn * Dd];
static __device__ __align__(16) __half g_Yh[(size_t)Mm * Dd];
static __device__ __align__(16) __half g_H[(size_t)Nn * Mm];   // (SC - off_i)*L2E
static __device__ __align__(16) __half g_HT[(size_t)Mm * Nn];
static __device__ float g_nx[Nn], g_ny[Mm], g_off[Nn];          // off in ln units
static __device__ float g_la[Nn], g_lb[Mm];                     // ln units
static __device__ float g_la2[Nn], g_lb2[Mm];                   // log2 units
static __device__ __align__(16) __half g_wah[Nn];               // wa2 (log2) fp16
static __device__ __align__(16) __half g_vbh[Mm];               // vb2 (log2) fp16
static __device__ float g_Lp[Nn];                               // prior row-LSE (phase A shift)
static __device__ float g_L2f[Nn], g_Lg2[Mm];                   // log2-LSE outputs
static __device__ float g_nybar;

__device__ __forceinline__ __half2 hexp2_(__half2 x) {
    uint32_t xi = *reinterpret_cast<uint32_t*>(&x), yi;
    asm("ex2.approx.f16x2 %0, %1;" : "=r"(yi) : "r"(xi));
    return *reinterpret_cast<__half2*>(&yi);
}
__device__ __forceinline__ uint32_t packh2(float a, float b) {
    __half2 h = __floats2half2_rn(a, b);
    return *reinterpret_cast<uint32_t*>(&h);
}
__device__ __forceinline__ void cpasync16(uint32_t smem_addr, const void* gptr) {
    asm volatile("cp.async.cg.shared.global [%0], [%1], 16;" :: "r"(smem_addr), "l"(gptr));
}
__device__ __forceinline__ void cpcommit() {
    asm volatile("cp.async.commit_group;" ::: "memory");
}
template <int N>
__device__ __forceinline__ void cpwait() {
    asm volatile("cp.async.wait_group %0;" :: "n"(N) : "memory");
}

__global__ void prep_kernel(const float* __restrict__ h, const float* __restrict__ hi) {
    int i = blockIdx.x * blockDim.x + threadIdx.x;
    if (i < Nn) { float l = logf(h[i]); g_la[i] = l; g_la2[i] = l * L2E; }
    if (i < Mm) {
        float l = logf(hi[i]);
        g_lb[i] = l; g_lb2[i] = l * L2E;
        g_vbh[i] = __float2half(l * L2E);
    }
}

#define D4 (Nn * Dd / 4)
#define S4 (Mm * Dd / 4)
#define W4 (Dd * Dd / 4)
__global__ void conv_kernel(const float* __restrict__ dp, const float* __restrict__ sip,
                            const float* __restrict__ Wp) {
    int idx = blockIdx.x * blockDim.x + threadIdx.x;
    const float* src; __half* dst; int q;
    if (idx < D4) { src = dp; dst = g_dh; q = idx; }
    else if (idx < D4 + S4) { src = sip; dst = g_sih; q = idx - D4; }
    else if (idx < D4 + S4 + W4) { src = Wp; dst = g_Wh; q = idx - D4 - S4; }
    else return;
    float4 v = ((const float4*)src)[q];
    ((uint2*)dst)[q] = make_uint2(packh2(v.x, v.y), packh2(v.z, v.w));
}

// ============ fp16 GEMM, tile 128x128, 256 thr, cp.async 2-stage pipeline ============
// EPI=0: merged projections. EPI=1: gram + cost epilogue -> g_H and g_HT.
template <int EPI>
__global__ void __launch_bounds__(256, 2) h_gemm() {
    __shared__ union SU {
        struct { __half As[2][128][72]; __half Bs[2][128][72]; } k;
        __half tile[128][136];
    } su;
    const int t = threadIdx.x, lane = t & 31, wid = t >> 5;
    const int wm = wid & 1, wn = wid >> 1;
    const int tg = lane & 3, gp = lane >> 2;

    const __half *A, *B;
    __half* Cout = nullptr;
    int bi, bj;
    if (EPI == 0) {
        const int by = blockIdx.y;
        if (by < Nn / 128) { A = g_dh; Cout = g_Xh; bi = by * 128; }
        else { A = g_sih; Cout = g_Yh; bi = (by - Nn / 128) * 128; }
        B = g_Wh; bj = blockIdx.x * 128;
    } else {
        A = g_Xh; B = g_Yh;
        bi = blockIdx.y * 128; bj = blockIdx.x * 128;
    }

    const int ar = t >> 1, side = (t & 1) * 32;   // 2 threads/row, 32 halves (4x16B) each
    const __half* Agp = A + (size_t)(bi + ar) * Dd + side;
    const __half* Bgp = B + (size_t)(bj + ar) * Dd + side;

    uint32_t sa[2], sb[2];
    #pragma unroll
    for (int st = 0; st < 2; st++) {
        sa[st] = (uint32_t)__cvta_generic_to_shared(&su.k.As[st][ar][side]);
        sb[st] = (uint32_t)__cvta_generic_to_shared(&su.k.Bs[st][ar][side]);
    }

    // prologue: load chunk 0 into stage 0
    #pragma unroll
    for (int q = 0; q < 4; q++) {
        cpasync16(sa[0] + 16 * q, Agp + 8 * q);
        cpasync16(sb[0] + 16 * q, Bgp + 8 * q);
    }
    cpcommit();

    float acc[4][4][4] = {};
    for (int ch = 0; ch < 12; ch++) {
        const int cb = ch & 1;
        if (ch < 11) {
            const int nb = (ch + 1) & 1;
            const int o = (ch + 1) * 64;   // halves
            #pragma unroll
            for (int q = 0; q < 4; q++) {
                cpasync16(sa[nb] + 16 * q, Agp + o + 8 * q);
                cpasync16(sb[nb] + 16 * q, Bgp + o + 8 * q);
            }
            cpcommit();
            cpwait<1>();
        } else {
            cpwait<0>();
        }
        __syncthreads();
        #pragma unroll
        for (int kk = 0; kk < 4; kk++) {
            const int kc = kk * 16;
            uint32_t ua[4][4], ub[4][2];
            #pragma unroll
            for (int im = 0; im < 4; im++) {
                const int rA = wm * 64 + im * 16 + gp;
                ua[im][0] = *(const uint32_t*)&su.k.As[cb][rA][kc + 2 * tg];
                ua[im][1] = *(const uint32_t*)&su.k.As[cb][rA + 8][kc + 2 * tg];
                ua[im][2] = *(const uint32_t*)&su.k.As[cb][rA][kc + 8 + 2 * tg];
                ua[im][3] = *(const uint32_t*)&su.k.As[cb][rA + 8][kc + 8 + 2 * tg];
            }
            #pragma unroll
            for (int jn = 0; jn < 4; jn++) {
                const int rB = wn * 32 + jn * 8 + gp;
                ub[jn][0] = *(const uint32_t*)&su.k.Bs[cb][rB][kc + 2 * tg];
                ub[jn][1] = *(const uint32_t*)&su.k.Bs[cb][rB][kc + 8 + 2 * tg];
            }
            #pragma unroll
            for (int im = 0; im < 4; im++)
                #pragma unroll
                for (int jn = 0; jn < 4; jn++)
                    asm volatile(
                        "mma.sync.aligned.m16n8k16.row.col.f32.f16.f16.f32 "
                        "{%0,%1,%2,%3}, {%4,%5,%6,%7}, {%8,%9}, {%0,%1,%2,%3};"
                        : "+f"(acc[im][jn][0]), "+f"(acc[im][jn][1]),
                          "+f"(acc[im][jn][2]), "+f"(acc[im][jn][3])
                        : "r"(ua[im][0]), "r"(ua[im][1]), "r"(ua[im][2]), "r"(ua[im][3]),
                          "r"(ub[jn][0]), "r"(ub[jn][1]));
        }
        __syncthreads();
    }

    if (EPI == 0) {
        #pragma unroll
        for (int im = 0; im < 4; im++) {
            const int r0 = bi + wm * 64 + im * 16 + gp;
            #pragma unroll
            for (int jn = 0; jn < 4; jn++) {
                const int cb2 = bj + wn * 32 + jn * 8 + 2 * tg;
                *(uint32_t*)&Cout[(size_t)r0 * Dd + cb2] = packh2(acc[im][jn][0], acc[im][jn][1]);
                *(uint32_t*)&Cout[(size_t)(r0 + 8) * Dd + cb2] = packh2(acc[im][jn][2], acc[im][jn][3]);
            }
        }
    } else {
        const float nyb = g_nybar;
        __half2 hv[4][4][2];
        #pragma unroll
        for (int im = 0; im < 4; im++) {
            const int rl = wm * 64 + im * 16 + gp;
            const float nx0 = g_nx[bi + rl], nx1 = g_nx[bi + rl + 8];
            const float o0 = SCL * (nx0 + nyb), o1 = SCL * (nx1 + nyb);
            #pragma unroll
            for (int jn = 0; jn < 4; jn++) {
                const int cl = wn * 32 + jn * 8 + 2 * tg;
                const float ny0 = g_ny[bj + cl], ny1 = g_ny[bj + cl + 1];
                float v00 = SCL * fmaxf(nx0 + ny0 - acc[im][jn][0], 0.f) - o0;
                float v01 = SCL * fmaxf(nx0 + ny1 - acc[im][jn][1], 0.f) - o0;
                float v10 = SCL * fmaxf(nx1 + ny0 - acc[im][jn][2], 0.f) - o1;
                float v11 = SCL * fmaxf(nx1 + ny1 - acc[im][jn][3], 0.f) - o1;
                hv[im][jn][0] = __floats2half2_rn(v00, v01);
                hv[im][jn][1] = __floats2half2_rn(v10, v11);
                *(__half2*)(g_H + (size_t)(bi + rl) * Mm + bj + cl) = hv[im][jn][0];
                *(__half2*)(g_H + (size_t)(bi + rl + 8) * Mm + bj + cl) = hv[im][jn][1];
            }
        }
        __syncthreads();
        #pragma unroll
        for (int im = 0; im < 4; im++) {
            const int rl = wm * 64 + im * 16 + gp;
            #pragma unroll
            for (int jn = 0; jn < 4; jn++) {
                const int cl = wn * 32 + jn * 8 + 2 * tg;
                su.tile[cl][rl]         = __low2half(hv[im][jn][0]);
                su.tile[cl + 1][rl]     = __high2half(hv[im][jn][0]);
                su.tile[cl][rl + 8]     = __low2half(hv[im][jn][1]);
                su.tile[cl + 1][rl + 8] = __high2half(hv[im][jn][1]);
            }
        }
        __syncthreads();
        const int c = t >> 1, rseg = (t & 1) * 64;
        const uint4* src = (const uint4*)&su.tile[c][rseg];
        uint4* dst = (uint4*)(g_HT + (size_t)(bj + c) * Nn + bi + rseg);
        #pragma unroll
        for (int q = 0; q < 8; q++) dst[q] = src[q];
    }
}

__global__ void __launch_bounds__(256) rownorm2() {
    const int gwarp = blockIdx.x * 8 + (threadIdx.x >> 5);
    const int lane = threadIdx.x & 31;
    const __half* X;
    float* outn;
    int row;
    if (gwarp < Nn) { X = g_Xh; outn = g_nx; row = gwarp; }
    else if (gwarp < Nn + Mm) { X = g_Yh; outn = g_ny; row = gwarp - Nn; }
    else return;
    const uint4* xr = (const uint4*)(X + (size_t)row * Dd);
    float s = 0.f;
    #pragma unroll
    for (int k = 0; k < 3; k++) {
        uint4 u = xr[lane + 32 * k];
        const __half2* hp = (const __half2*)&u;
        #pragma unroll
        for (int c = 0; c < 4; c++) {
            float2 f = __half22float2(hp[c]);
            s = fmaf(f.x, f.x, s); s = fmaf(f.y, f.y, s);
        }
    }
    #pragma unroll
    for (int o = 16; o > 0; o >>= 1) s += __shfl_xor_sync(0xffffffffu, s, o);
    if (lane == 0) outn[row] = 0.5f * s;
}

// single block: nybar reduction then off vector (fused)
__global__ void __launch_bounds__(1024) nybar_off_kernel() {
    const int t = threadIdx.x;
    float s = 0.f;
    for (int j = t; j < Mm; j += 1024) s += g_ny[j];
    __shared__ float sd[1024];
    sd[t] = s; __syncthreads();
    for (int o = 512; o > 0; o >>= 1) { if (t < o) sd[t] += sd[t + o]; __syncthreads(); }
    const float nyb = sd[0] / (float)Mm;
    if (t == 0) g_nybar = nyb;
    for (int i = t; i < Nn; i += 1024) g_off[i] = 400.f * (g_nx[i] + nyb);
}

// ===== phase A warmup: two-pass softmin over H rows (1 warp/row); stores L to g_Lp =====
__global__ void __launch_bounds__(256) softminA_w() {
    const int t = threadIdx.x, lane = t & 31, wid = t >> 5;
    const int row = blockIdx.x * 8 + wid;
    const uint4* Hr = (const uint4*)(g_H + (size_t)row * Mm);
    const uint4* Vr = (const uint4*)g_vbh;

    __half2 a[8][4];
    __half2 m2 = __float2half2_rn(-60000.f);
    #pragma unroll
    for (int q = 0; q < 8; q++) {
        const int idx = q * 32 + lane;
        uint4 hu = Hr[idx];
        uint4 vu = __ldg(&Vr[idx]);
        const __half2* hp = (const __half2*)&hu;
        const __half2* vp = (const __half2*)&vu;
        #pragma unroll
        for (int c = 0; c < 4; c++) {
            a[q][c] = __hsub2(vp[c], hp[c]);
            m2 = __hmax2(m2, a[q][c]);
        }
    }
    float m = fmaxf(__half2float(__low2half(m2)), __half2float(__high2half(m2)));
    #pragma unroll
    for (int o = 16; o > 0; o >>= 1) m = fmaxf(m, __shfl_xor_sync(0xffffffffu, m, o));
    const __half2 mh = __float2half2_rn(m);

    float s0 = 0.f, s1 = 0.f;
    #pragma unroll
    for (int q = 0; q < 8; q++) {
        __half2 p = __float2half2_rn(0.f);
        #pragma unroll
        for (int c = 0; c < 4; c++) p = __hadd2(p, hexp2_(__hsub2(a[q][c], mh)));
        float pf = __half2float(__hadd(__low2half(p), __high2half(p)));
        if (q & 1) s1 += pf; else s0 += pf;
    }
    float s = s0 + s1;
    #pragma unroll
    for (int o = 16; o > 0; o >>= 1) s += __shfl_xor_sync(0xffffffffu, s, o);
    if (lane == 0) {
        float L = m + __log2f(s);
        g_Lp[row] = L;
        g_wah[row] = __float2half(g_la2[row] - L);
    }
}

// ===== phase A steady: ONE-PASS shifted by prior L (1 warp/row, 8 rows/block) =====
template <int FINAL>
__global__ void __launch_bounds__(256) softminA1() {
    const int t = threadIdx.x, lane = t & 31, wid = t >> 5;
    const int row = blockIdx.x * 8 + wid;
    const uint4* Hr = (const uint4*)(g_H + (size_t)row * Mm);
    const uint4* Vr = (const uint4*)g_vbh;
    const float Lp = g_Lp[row];
    const __half2 Lp2 = __float2half2_rn(Lp);

    float s0 = 0.f, s1 = 0.f;
    #pragma unroll
    for (int q = 0; q < 8; q++) {
        const int idx = q * 32 + lane;
        uint4 hu = Hr[idx];
        uint4 vu = __ldg(&Vr[idx]);
        const __half2* hp = (const __half2*)&hu;
        const __half2* vp = (const __half2*)&vu;
        __half2 p = __float2half2_rn(0.f);
        #pragma unroll
        for (int c = 0; c < 4; c++)
            p = __hadd2(p, hexp2_(__hsub2(__hsub2(vp[c], hp[c]), Lp2)));
        float pf = __half2float(__hadd(__low2half(p), __high2half(p)));
        if (q & 1) s1 += pf; else s0 += pf;
    }
    float s = s0 + s1;
    #pragma unroll
    for (int o = 16; o > 0; o >>= 1) s += __shfl_xor_sync(0xffffffffu, s, o);
    if (lane == 0) {
        float L = Lp + __log2f(s);
        g_Lp[row] = L;
        if (FINAL) g_L2f[row] = L;
        else g_wah[row] = __float2half(g_la2[row] - L);
    }
}

// ===== phase B warmup: two-pass over HT rows (4 warps/row, 2 rows/block) =====
__global__ void __launch_bounds__(256) softminB_w() {
    __shared__ float sM[2][4], sS[2][4];
    const int t = threadIdx.x, lane = t & 31, wid = t >> 5;
    const int rloc = wid >> 2, quarter = wid & 3;
    const int row = blockIdx.x * 2 + rloc;
    const uint4* Hr = (const uint4*)(g_HT + (size_t)row * Nn);
    const uint4* Vr = (const uint4*)g_wah;

    __half2 a[8][4];
    __half2 m2 = __float2half2_rn(-60000.f);
    #pragma unroll
    for (int q = 0; q < 8; q++) {
        const int idx = quarter * 256 + q * 32 + lane;
        uint4 hu = Hr[idx];
        uint4 vu = __ldg(&Vr[idx]);
        const __half2* hp = (const __half2*)&hu;
        const __half2* vp = (const __half2*)&vu;
        #pragma unroll
        for (int c = 0; c < 4; c++) {
            a[q][c] = __hsub2(vp[c], hp[c]);
            m2 = __hmax2(m2, a[q][c]);
        }
    }
    float m = fmaxf(__half2float(__low2half(m2)), __half2float(__high2half(m2)));
    #pragma unroll
    for (int o = 16; o > 0; o >>= 1) m = fmaxf(m, __shfl_xor_sync(0xffffffffu, m, o));
    const __half2 mh = __float2half2_rn(m);

    float s0 = 0.f, s1 = 0.f;
    #pragma unroll
    for (int q = 0; q < 8; q++) {
        __half2 p = __float2half2_rn(0.f);
        #pragma unroll
        for (int c = 0; c < 4; c++) p = __hadd2(p, hexp2_(__hsub2(a[q][c], mh)));
        float pf = __half2float(__hadd(__low2half(p), __high2half(p)));
        if (q & 1) s1 += pf; else s0 += pf;
    }
    float s = s0 + s1;
    #pragma unroll
    for (int o = 16; o > 0; o >>= 1) s += __shfl_xor_sync(0xffffffffu, s, o);

    if (lane == 0) { sM[rloc][quarter] = m; sS[rloc][quarter] = s; }
    __syncthreads();
    if (t < 2) {
        float M2 = sM[t][0];
        #pragma unroll
        for (int w = 1; w < 4; w++) M2 = fmaxf(M2, sM[t][w]);
        float S2 = 0.f;
        #pragma unroll
        for (int w = 0; w < 4; w++) S2 += sS[t][w] * exp2f(sM[t][w] - M2);
        float L = M2 + __log2f(S2);
        const int r = blockIdx.x * 2 + t;
        g_vbh[r] = __float2half(g_lb2[r] - L);
        g_Lg2[r] = L;
    }
}

// ===== phase B steady: ONE-PASS shifted by prior Lg2 (4 warps/row, 2 rows/block) =====
__global__ void __launch_bounds__(256) softminB1() {
    __shared__ float sS[2][4];
    const int t = threadIdx.x, lane = t & 31, wid = t >> 5;
    const int rloc = wid >> 2, quarter = wid & 3;
    const int row = blockIdx.x * 2 + rloc;
    const uint4* Hr = (const uint4*)(g_HT + (size_t)row * Nn);
    const uint4* Vr = (const uint4*)g_wah;
    const __half2 Lp2 = __float2half2_rn(g_Lg2[row]);

    float s0 = 0.f, s1 = 0.f;
    #pragma unroll
    for (int q = 0; q < 8; q++) {
        const int idx = quarter * 256 + q * 32 + lane;
        uint4 hu = Hr[idx];
        uint4 vu = __ldg(&Vr[idx]);
        const __half2* hp = (const __half2*)&hu;
        const __half2* vp = (const __half2*)&vu;
        __half2 p = __float2half2_rn(0.f);
        #pragma unroll
        for (int c = 0; c < 4; c++)
            p = __hadd2(p, hexp2_(__hsub2(__hsub2(vp[c], hp[c]), Lp2)));
        float pf = __half2float(__hadd(__low2half(p), __high2half(p)));
        if (q & 1) s1 += pf; else s0 += pf;
    }
    float s = s0 + s1;
    #pragma unroll
    for (int o = 16; o > 0; o >>= 1) s += __shfl_xor_sync(0xffffffffu, s, o);

    if (lane == 0) sS[rloc][quarter] = s;
    __syncthreads();
    if (t < 2) {
        const int r = blockIdx.x * 2 + t;
        float S2 = sS[t][0] + sS[t][1] + sS[t][2] + sS[t][3];
        float L = g_Lg2[r] + __log2f(S2);
        g_vbh[r] = __float2half(g_lb2[r] - L);
        g_Lg2[r] = L;
    }
}

__global__ void final_kernel(const float* __restrict__ h, const float* __restrict__ hi,
                             float* __restrict__ out) {
    const int t = threadIdx.x;
    double acc = 0.0;
    for (int i = t; i < Nn; i += 256)
        acc += (double)h[i] * (LN2 * (double)g_L2f[i] - (double)g_off[i] - 0.5 * (double)g_la[i]);
    for (int j = t; j < Mm; j += 256)
        acc += (double)hi[j] * (LN2 * (double)g_Lg2[j] - 0.5 * (double)g_lb[j]);
    __shared__ double sd[256];
    sd[t] = acc; __syncthreads();
    for (int o = 128; o > 0; o >>= 1) { if (t < o) sd[t] += sd[t + o]; __syncthreads(); }
    if (t == 0) out[0] = (float)exp(EPS_D * sd[0]);
}

extern "C" void kernel_launch(void* const* d_in, const int* in_sizes, int n_in,
                              void* d_out, int out_size) {
    const float *dp = nullptr, *sip = nullptr, *hp = nullptr, *hip = nullptr, *Wp = nullptr;
    for (int i = 0; i < n_in; i++) {
        switch (in_sizes[i]) {
            case Nn * Dd: dp  = (const float*)d_in[i]; break;
            case Mm * Dd: sip = (const float*)d_in[i]; break;
            case Nn:      hp  = (const float*)d_in[i]; break;
            case Mm:      hip = (const float*)d_in[i]; break;
            case Dd * Dd: Wp  = (const float*)d_in[i]; break;
        }
    }
    if (!dp)  dp  = (const float*)d_in[0];
    if (!sip) sip = (const float*)d_in[1];
    if (!hp)  hp  = (const float*)d_in[2];
    if (!hip) hip = (const float*)d_in[3];
    if (!Wp)  Wp  = (const float*)d_in[4];

    prep_kernel<<<(Nn + 255) / 256, 256>>>(hp, hip);
    conv_kernel<<<(D4 + S4 + W4 + 255) / 256, 256>>>(dp, sip, Wp);
    h_gemm<0><<<dim3(Dd / 128, (Nn + Mm) / 128), 256>>>();   // merged projections
    rownorm2<<<(Nn + Mm) / 8, 256>>>();
    nybar_off_kernel<<<1, 1024>>>();
    h_gemm<1><<<dim3(Mm / 128, Nn / 128), 256>>>();          // gram + cost epilogue

    for (int it = 0; it < 4; it++) {
        softminA_w<<<Nn / 8, 256>>>();
        softminB_w<<<Mm / 2, 256>>>();
    }
    for (int it = 4; it < 50; it++) {
        softminA1<0><<<Nn / 8, 256>>>();
        softminB1<<<Mm / 2, 256>>>();
    }
    softminA1<1><<<Nn / 8, 256>>>();

    final_kernel<<<1, 256>>>(hp, hip, (float*)d_out);
}

// round 16
// speedup vs baseline: 1.1525x; 1.1525x over previous
#include <cuda_runtime.h>
#include <cuda_fp16.h>
#include <math.h>
#include <stdint.h>

#define Nn 8192
#define Mm 2048
#define Dd 768
#define EPS_D 0.0025
#define L2E 1.4426950408889634f
#define LN2 0.6931471805599453
#define SCL (400.0f * L2E)   // cost scale in log2 units

static __device__ __align__(16) __half g_dh[(size_t)Nn * Dd];
static __device__ __align__(16) __half g_sih[(size_t)Mm * Dd];
static __device__ __align__(16) __half g_Wh[(size_t)Dd * Dd];
static __device__ __align__(16) __half g_Xh[(size_t)Nn * Dd];
static __device__ __align__(16) __half g_Yh[(size_t)Mm * Dd];
static __device__ __align__(16) __half g_H[(size_t)Nn * Mm];   // (SC - off_i)*L2E
static __device__ __align__(16) __half g_HT[(size_t)Mm * Nn];
static __device__ float g_nx[Nn], g_ny[Mm], g_off[Nn];          // off in ln units
static __device__ float g_la[Nn], g_lb[Mm];                     // ln units
static __device__ float g_la2[Nn], g_lb2[Mm];                   // log2 units
static __device__ __align__(16) __half g_wah[Nn];               // wa2 (log2) fp16
static __device__ __align__(16) __half g_vbh[Mm];               // vb2 (log2) fp16
static __device__ float g_Lp[Nn];                               // prior row-LSE (phase A shift)
static __device__ float g_L2f[Nn], g_Lg2[Mm];                   // log2-LSE outputs
static __device__ float g_nybar;

__device__ __forceinline__ __half2 hexp2_(__half2 x) {
    uint32_t xi = *reinterpret_cast<uint32_t*>(&x), yi;
    asm("ex2.approx.f16x2 %0, %1;" : "=r"(yi) : "r"(xi));
    return *reinterpret_cast<__half2*>(&yi);
}
__device__ __forceinline__ uint32_t packh2(float a, float b) {
    __half2 h = __floats2half2_rn(a, b);
    return *reinterpret_cast<uint32_t*>(&h);
}

__global__ void prep_kernel(const float* __restrict__ h, const float* __restrict__ hi) {
    int i = blockIdx.x * blockDim.x + threadIdx.x;
    if (i < Nn) { float l = logf(h[i]); g_la[i] = l; g_la2[i] = l * L2E; }
    if (i < Mm) {
        float l = logf(hi[i]);
        g_lb[i] = l; g_lb2[i] = l * L2E;
        g_vbh[i] = __float2half(l * L2E);
    }
}

// fp32 -> fp16 conversion of d, si, W (float4 granularity)
#define D4 (Nn * Dd / 4)
#define S4 (Mm * Dd / 4)
#define W4 (Dd * Dd / 4)
__global__ void conv_kernel(const float* __restrict__ dp, const float* __restrict__ sip,
                            const float* __restrict__ Wp) {
    int idx = blockIdx.x * blockDim.x + threadIdx.x;
    const float* src; __half* dst; int q;
    if (idx < D4) { src = dp; dst = g_dh; q = idx; }
    else if (idx < D4 + S4) { src = sip; dst = g_sih; q = idx - D4; }
    else if (idx < D4 + S4 + W4) { src = Wp; dst = g_Wh; q = idx - D4 - S4; }
    else return;
    float4 v = ((const float4*)src)[q];
    ((uint2*)dst)[q] = make_uint2(packh2(v.x, v.y), packh2(v.z, v.w));
}

// ============ fp16 GEMM, tile 128x128, 256 thr, 2 blocks/SM ============
// EPI=0: merged projections (by<64 -> Xh rows of d, else Yh rows of si).
// EPI=1: gram Xh@Yh^T with cost epilogue -> g_H and g_HT.
template <int EPI>
__global__ void __launch_bounds__(256, 2) h_gemm() {
    __shared__ union SU {
        struct { __half As[128][72]; __half Bs[128][72]; } k;
        __half tile[128][136];
    } su;
    const int t = threadIdx.x, lane = t & 31, wid = t >> 5;
    const int wm = wid & 1, wn = wid >> 1;
    const int tg = lane & 3, gp = lane >> 2;

    const __half *A, *B;
    __half* Cout = nullptr;
    int bi, bj;
    if (EPI == 0) {
        const int by = blockIdx.y;
        if (by < Nn / 128) { A = g_dh; Cout = g_Xh; bi = by * 128; }
        else { A = g_sih; Cout = g_Yh; bi = (by - Nn / 128) * 128; }
        B = g_Wh; bj = blockIdx.x * 128;
    } else {
        A = g_Xh; B = g_Yh;
        bi = blockIdx.y * 128; bj = blockIdx.x * 128;
    }

    const int ar = t >> 1, side = (t & 1) * 32;
    float acc[4][4][4] = {};
    const uint4* Ap = (const uint4*)(A + (size_t)(bi + ar) * Dd + side);
    const uint4* Bp = (const uint4*)(B + (size_t)(bj + ar) * Dd + side);
    uint4 pa[4], pb[4];
    #pragma unroll
    for (int q = 0; q < 4; q++) { pa[q] = Ap[q]; pb[q] = Bp[q]; }

    for (int ch = 0; ch < 12; ch++) {
        #pragma unroll
        for (int q = 0; q < 4; q++) {
            *(uint4*)&su.k.As[ar][side + 8 * q] = pa[q];
            *(uint4*)&su.k.Bs[ar][side + 8 * q] = pb[q];
        }
        __syncthreads();
        if (ch < 11) {
            const int o = (ch + 1) * 8;
            #pragma unroll
            for (int q = 0; q < 4; q++) { pa[q] = Ap[o + q]; pb[q] = Bp[o + q]; }
        }
        #pragma unroll
        for (int kk = 0; kk < 4; kk++) {
            const int kc = kk * 16;
            uint32_t ua[4][4], ub[4][2];
            #pragma unroll
            for (int im = 0; im < 4; im++) {
                const int rA = wm * 64 + im * 16 + gp;
                ua[im][0] = *(const uint32_t*)&su.k.As[rA][kc + 2 * tg];
                ua[im][1] = *(const uint32_t*)&su.k.As[rA + 8][kc + 2 * tg];
                ua[im][2] = *(const uint32_t*)&su.k.As[rA][kc + 8 + 2 * tg];
                ua[im][3] = *(const uint32_t*)&su.k.As[rA + 8][kc + 8 + 2 * tg];
            }
            #pragma unroll
            for (int jn = 0; jn < 4; jn++) {
                const int rB = wn * 32 + jn * 8 + gp;
                ub[jn][0] = *(const uint32_t*)&su.k.Bs[rB][kc + 2 * tg];
                ub[jn][1] = *(const uint32_t*)&su.k.Bs[rB][kc + 8 + 2 * tg];
            }
            #pragma unroll
            for (int im = 0; im < 4; im++)
                #pragma unroll
                for (int jn = 0; jn < 4; jn++)
                    asm volatile(
                        "mma.sync.aligned.m16n8k16.row.col.f32.f16.f16.f32 "
                        "{%0,%1,%2,%3}, {%4,%5,%6,%7}, {%8,%9}, {%0,%1,%2,%3};"
                        : "+f"(acc[im][jn][0]), "+f"(acc[im][jn][1]),
                          "+f"(acc[im][jn][2]), "+f"(acc[im][jn][3])
                        : "r"(ua[im][0]), "r"(ua[im][1]), "r"(ua[im][2]), "r"(ua[im][3]),
                          "r"(ub[jn][0]), "r"(ub[jn][1]));
        }
        __syncthreads();
    }

    if (EPI == 0) {
        #pragma unroll
        for (int im = 0; im < 4; im++) {
            const int r0 = bi + wm * 64 + im * 16 + gp;
            #pragma unroll
            for (int jn = 0; jn < 4; jn++) {
                const int cb = bj + wn * 32 + jn * 8 + 2 * tg;
                *(uint32_t*)&Cout[(size_t)r0 * Dd + cb] = packh2(acc[im][jn][0], acc[im][jn][1]);
                *(uint32_t*)&Cout[(size_t)(r0 + 8) * Dd + cb] = packh2(acc[im][jn][2], acc[im][jn][3]);
            }
        }
    } else {
        const float nyb = g_nybar;
        __half2 hv[4][4][2];
        #pragma unroll
        for (int im = 0; im < 4; im++) {
            const int rl = wm * 64 + im * 16 + gp;
            const float nx0 = g_nx[bi + rl], nx1 = g_nx[bi + rl + 8];
            const float o0 = SCL * (nx0 + nyb), o1 = SCL * (nx1 + nyb);
            #pragma unroll
            for (int jn = 0; jn < 4; jn++) {
                const int cl = wn * 32 + jn * 8 + 2 * tg;
                const float ny0 = g_ny[bj + cl], ny1 = g_ny[bj + cl + 1];
                float v00 = SCL * fmaxf(nx0 + ny0 - acc[im][jn][0], 0.f) - o0;
                float v01 = SCL * fmaxf(nx0 + ny1 - acc[im][jn][1], 0.f) - o0;
                float v10 = SCL * fmaxf(nx1 + ny0 - acc[im][jn][2], 0.f) - o1;
                float v11 = SCL * fmaxf(nx1 + ny1 - acc[im][jn][3], 0.f) - o1;
                hv[im][jn][0] = __floats2half2_rn(v00, v01);
                hv[im][jn][1] = __floats2half2_rn(v10, v11);
                *(__half2*)(g_H + (size_t)(bi + rl) * Mm + bj + cl) = hv[im][jn][0];
                *(__half2*)(g_H + (size_t)(bi + rl + 8) * Mm + bj + cl) = hv[im][jn][1];
            }
        }
        __syncthreads();
        #pragma unroll
        for (int im = 0; im < 4; im++) {
            const int rl = wm * 64 + im * 16 + gp;
            #pragma unroll
            for (int jn = 0; jn < 4; jn++) {
                const int cl = wn * 32 + jn * 8 + 2 * tg;
                su.tile[cl][rl]         = __low2half(hv[im][jn][0]);
                su.tile[cl + 1][rl]     = __high2half(hv[im][jn][0]);
                su.tile[cl][rl + 8]     = __low2half(hv[im][jn][1]);
                su.tile[cl + 1][rl + 8] = __high2half(hv[im][jn][1]);
            }
        }
        __syncthreads();
        const int c = t >> 1, rseg = (t & 1) * 64;
        const uint4* src = (const uint4*)&su.tile[c][rseg];
        uint4* dst = (uint4*)(g_HT + (size_t)(bj + c) * Nn + bi + rseg);
        #pragma unroll
        for (int q = 0; q < 8; q++) dst[q] = src[q];
    }
}

__global__ void __launch_bounds__(256) rownorm2() {
    const int gwarp = blockIdx.x * 8 + (threadIdx.x >> 5);
    const int lane = threadIdx.x & 31;
    const __half* X;
    float* outn;
    int row;
    if (gwarp < Nn) { X = g_Xh; outn = g_nx; row = gwarp; }
    else if (gwarp < Nn + Mm) { X = g_Yh; outn = g_ny; row = gwarp - Nn; }
    else return;
    const uint4* xr = (const uint4*)(X + (size_t)row * Dd);
    float s = 0.f;
    #pragma unroll
    for (int k = 0; k < 3; k++) {
        uint4 u = xr[lane + 32 * k];
        const __half2* hp = (const __half2*)&u;
        #pragma unroll
        for (int c = 0; c < 4; c++) {
            float2 f = __half22float2(hp[c]);
            s = fmaf(f.x, f.x, s); s = fmaf(f.y, f.y, s);
        }
    }
    #pragma unroll
    for (int o = 16; o > 0; o >>= 1) s += __shfl_xor_sync(0xffffffffu, s, o);
    if (lane == 0) outn[row] = 0.5f * s;
}

// single block: nybar reduction then off vector (fused)
__global__ void __launch_bounds__(1024) nybar_off_kernel() {
    const int t = threadIdx.x;
    float s = 0.f;
    for (int j = t; j < Mm; j += 1024) s += g_ny[j];
    __shared__ float sd[1024];
    sd[t] = s; __syncthreads();
    for (int o = 512; o > 0; o >>= 1) { if (t < o) sd[t] += sd[t + o]; __syncthreads(); }
    const float nyb = sd[0] / (float)Mm;
    if (t == 0) g_nybar = nyb;
    for (int i = t; i < Nn; i += 1024) g_off[i] = 400.f * (g_nx[i] + nyb);
}

// ===== phase A warmup: two-pass softmin over H rows (1 warp/row); stores L to g_Lp =====
__global__ void __launch_bounds__(256) softminA_w() {
    const int t = threadIdx.x, lane = t & 31, wid = t >> 5;
    const int row = blockIdx.x * 8 + wid;
    const uint4* Hr = (const uint4*)(g_H + (size_t)row * Mm);
    const uint4* Vr = (const uint4*)g_vbh;

    __half2 a[8][4];
    __half2 m2 = __float2half2_rn(-60000.f);
    #pragma unroll
    for (int q = 0; q < 8; q++) {
        const int idx = q * 32 + lane;
        uint4 hu = Hr[idx];
        uint4 vu = __ldg(&Vr[idx]);
        const __half2* hp = (const __half2*)&hu;
        const __half2* vp = (const __half2*)&vu;
        #pragma unroll
        for (int c = 0; c < 4; c++) {
            a[q][c] = __hsub2(vp[c], hp[c]);
            m2 = __hmax2(m2, a[q][c]);
        }
    }
    float m = fmaxf(__half2float(__low2half(m2)), __half2float(__high2half(m2)));
    #pragma unroll
    for (int o = 16; o > 0; o >>= 1) m = fmaxf(m, __shfl_xor_sync(0xffffffffu, m, o));
    const __half2 mh = __float2half2_rn(m);

    float s0 = 0.f, s1 = 0.f;
    #pragma unroll
    for (int q = 0; q < 8; q++) {
        __half2 p = __float2half2_rn(0.f);
        #pragma unroll
        for (int c = 0; c < 4; c++) p = __hadd2(p, hexp2_(__hsub2(a[q][c], mh)));
        float pf = __half2float(__hadd(__low2half(p), __high2half(p)));
        if (q & 1) s1 += pf; else s0 += pf;
    }
    float s = s0 + s1;
    #pragma unroll
    for (int o = 16; o > 0; o >>= 1) s += __shfl_xor_sync(0xffffffffu, s, o);
    if (lane == 0) {
        float L = m + __log2f(s);
        g_Lp[row] = L;
        g_wah[row] = __float2half(g_la2[row] - L);
    }
}

// ===== phase A steady: ONE-PASS shifted by prior L (1 warp/row, 8 rows/block) =====
template <int FINAL>
__global__ void __launch_bounds__(256) softminA1() {
    const int t = threadIdx.x, lane = t & 31, wid = t >> 5;
    const int row = blockIdx.x * 8 + wid;
    const uint4* Hr = (const uint4*)(g_H + (size_t)row * Mm);
    const uint4* Vr = (const uint4*)g_vbh;
    const float Lp = g_Lp[row];
    const __half2 Lp2 = __float2half2_rn(Lp);

    float s0 = 0.f, s1 = 0.f;
    #pragma unroll
    for (int q = 0; q < 8; q++) {
        const int idx = q * 32 + lane;
        uint4 hu = Hr[idx];
        uint4 vu = __ldg(&Vr[idx]);
        const __half2* hp = (const __half2*)&hu;
        const __half2* vp = (const __half2*)&vu;
        __half2 p = __float2half2_rn(0.f);
        #pragma unroll
        for (int c = 0; c < 4; c++)
            p = __hadd2(p, hexp2_(__hsub2(__hsub2(vp[c], hp[c]), Lp2)));
        float pf = __half2float(__hadd(__low2half(p), __high2half(p)));
        if (q & 1) s1 += pf; else s0 += pf;
    }
    float s = s0 + s1;
    #pragma unroll
    for (int o = 16; o > 0; o >>= 1) s += __shfl_xor_sync(0xffffffffu, s, o);
    if (lane == 0) {
        float L = Lp + __log2f(s);
        g_Lp[row] = L;
        if (FINAL) g_L2f[row] = L;
        else g_wah[row] = __float2half(g_la2[row] - L);
    }
}

// ===== phase B warmup: two-pass over HT rows (4 warps/row, 2 rows/block) =====
__global__ void __launch_bounds__(256) softminB_w() {
    __shared__ float sM[2][4], sS[2][4];
    const int t = threadIdx.x, lane = t & 31, wid = t >> 5;
    const int rloc = wid >> 2, quarter = wid & 3;
    const int row = blockIdx.x * 2 + rloc;
    const uint4* Hr = (const uint4*)(g_HT + (size_t)row * Nn);
    const uint4* Vr = (const uint4*)g_wah;

    __half2 a[8][4];
    __half2 m2 = __float2half2_rn(-60000.f);
    #pragma unroll
    for (int q = 0; q < 8; q++) {
        const int idx = quarter * 256 + q * 32 + lane;
        uint4 hu = Hr[idx];
        uint4 vu = __ldg(&Vr[idx]);
        const __half2* hp = (const __half2*)&hu;
        const __half2* vp = (const __half2*)&vu;
        #pragma unroll
        for (int c = 0; c < 4; c++) {
            a[q][c] = __hsub2(vp[c], hp[c]);
            m2 = __hmax2(m2, a[q][c]);
        }
    }
    float m = fmaxf(__half2float(__low2half(m2)), __half2float(__high2half(m2)));
    #pragma unroll
    for (int o = 16; o > 0; o >>= 1) m = fmaxf(m, __shfl_xor_sync(0xffffffffu, m, o));
    const __half2 mh = __float2half2_rn(m);

    float s0 = 0.f, s1 = 0.f;
    #pragma unroll
    for (int q = 0; q < 8; q++) {
        __half2 p = __float2half2_rn(0.f);
        #pragma unroll
        for (int c = 0; c < 4; c++) p = __hadd2(p, hexp2_(__hsub2(a[q][c], mh)));
        float pf = __half2float(__hadd(__low2half(p), __high2half(p)));
        if (q & 1) s1 += pf; else s0 += pf;
    }
    float s = s0 + s1;
    #pragma unroll
    for (int o = 16; o > 0; o >>= 1) s += __shfl_xor_sync(0xffffffffu, s, o);

    if (lane == 0) { sM[rloc][quarter] = m; sS[rloc][quarter] = s; }
    __syncthreads();
    if (t < 2) {
        float M2 = sM[t][0];
        #pragma unroll
        for (int w = 1; w < 4; w++) M2 = fmaxf(M2, sM[t][w]);
        float S2 = 0.f;
        #pragma unroll
        for (int w = 0; w < 4; w++) S2 += sS[t][w] * exp2f(sM[t][w] - M2);
        float L = M2 + __log2f(S2);
        const int r = blockIdx.x * 2 + t;
        g_vbh[r] = __float2half(g_lb2[r] - L);
        g_Lg2[r] = L;
    }
}

// ===== phase B steady: ONE-PASS shifted by prior Lg2 (4 warps/row, 2 rows/block) =====
__global__ void __launch_bounds__(256) softminB1() {
    __shared__ float sS[2][4];
    const int t = threadIdx.x, lane = t & 31, wid = t >> 5;
    const int rloc = wid >> 2, quarter = wid & 3;
    const int row = blockIdx.x * 2 + rloc;
    const uint4* Hr = (const uint4*)(g_HT + (size_t)row * Nn);
    const uint4* Vr = (const uint4*)g_wah;
    const __half2 Lp2 = __float2half2_rn(g_Lg2[row]);

    float s0 = 0.f, s1 = 0.f;
    #pragma unroll
    for (int q = 0; q < 8; q++) {
        const int idx = quarter * 256 + q * 32 + lane;
        uint4 hu = Hr[idx];
        uint4 vu = __ldg(&Vr[idx]);
        const __half2* hp = (const __half2*)&hu;
        const __half2* vp = (const __half2*)&vu;
        __half2 p = __float2half2_rn(0.f);
        #pragma unroll
        for (int c = 0; c < 4; c++)
            p = __hadd2(p, hexp2_(__hsub2(__hsub2(vp[c], hp[c]), Lp2)));
        float pf = __half2float(__hadd(__low2half(p), __high2half(p)));
        if (q & 1) s1 += pf; else s0 += pf;
    }
    float s = s0 + s1;
    #pragma unroll
    for (int o = 16; o > 0; o >>= 1) s += __shfl_xor_sync(0xffffffffu, s, o);

    if (lane == 0) sS[rloc][quarter] = s;
    __syncthreads();
    if (t < 2) {
        const int r = blockIdx.x * 2 + t;
        float S2 = sS[t][0] + sS[t][1] + sS[t][2] + sS[t][3];
        float L = g_Lg2[r] + __log2f(S2);
        g_vbh[r] = __float2half(g_lb2[r] - L);
        g_Lg2[r] = L;
    }
}

__global__ void final_kernel(const float* __restrict__ h, const float* __restrict__ hi,
                             float* __restrict__ out) {
    const int t = threadIdx.x;
    double acc = 0.0;
    for (int i = t; i < Nn; i += 256)
        acc += (double)h[i] * (LN2 * (double)g_L2f[i] - (double)g_off[i] - 0.5 * (double)g_la[i]);
    for (int j = t; j < Mm; j += 256)
        acc += (double)hi[j] * (LN2 * (double)g_Lg2[j] - 0.5 * (double)g_lb[j]);
    __shared__ double sd[256];
    sd[t] = acc; __syncthreads();
    for (int o = 128; o > 0; o >>= 1) { if (t < o) sd[t] += sd[t + o]; __syncthreads(); }
    if (t == 0) out[0] = (float)exp(EPS_D * sd[0]);
}

extern "C" void kernel_launch(void* const* d_in, const int* in_sizes, int n_in,
                              void* d_out, int out_size) {
    const float *dp = nullptr, *sip = nullptr, *hp = nullptr, *hip = nullptr, *Wp = nullptr;
    for (int i = 0; i < n_in; i++) {
        switch (in_sizes[i]) {
            case Nn * Dd: dp  = (const float*)d_in[i]; break;
            case Mm * Dd: sip = (const float*)d_in[i]; break;
            case Nn:      hp  = (const float*)d_in[i]; break;
            case Mm:      hip = (const float*)d_in[i]; break;
            case Dd * Dd: Wp  = (const float*)d_in[i]; break;
        }
    }
    if (!dp)  dp  = (const float*)d_in[0];
    if (!sip) sip = (const float*)d_in[1];
    if (!hp)  hp  = (const float*)d_in[2];
    if (!hip) hip = (const float*)d_in[3];
    if (!Wp)  Wp  = (const float*)d_in[4];

    prep_kernel<<<(Nn + 255) / 256, 256>>>(hp, hip);
    conv_kernel<<<(D4 + S4 + W4 + 255) / 256, 256>>>(dp, sip, Wp);
    h_gemm<0><<<dim3(Dd / 128, (Nn + Mm) / 128), 256>>>();   // merged projections
    rownorm2<<<(Nn + Mm) / 8, 256>>>();
    nybar_off_kernel<<<1, 1024>>>();
    h_gemm<1><<<dim3(Mm / 128, Nn / 128), 256>>>();          // gram + cost epilogue

    for (int it = 0; it < 4; it++) {
        softminA_w<<<Nn / 8, 256>>>();
        softminB_w<<<Mm / 2, 256>>>();
    }
    for (int it = 4; it < 40; it++) {
        softminA1<0><<<Nn / 8, 256>>>();
        softminB1<<<Mm / 2, 256>>>();
    }
    softminA1<1><<<Nn / 8, 256>>>();

    final_kernel<<<1, 256>>>(hp, hip, (float*)d_out);
}

// round 17
// speedup vs baseline: 1.2929x; 1.1218x over previous
#include <cuda_runtime.h>
#include <cuda_fp16.h>
#include <math.h>
#include <stdint.h>

#define Nn 8192
#define Mm 2048
#define Dd 768
#define EPS_D 0.0025
#define L2E 1.4426950408889634f
#define LN2 0.6931471805599453
#define SCL (400.0f * L2E)   // cost scale in log2 units

static __device__ __align__(16) __half g_dh[(size_t)Nn * Dd];
static __device__ __align__(16) __half g_sih[(size_t)Mm * Dd];
static __device__ __align__(16) __half g_Wh[(size_t)Dd * Dd];
static __device__ __align__(16) __half g_Xh[(size_t)Nn * Dd];
static __device__ __align__(16) __half g_Yh[(size_t)Mm * Dd];
static __device__ __align__(16) __half g_H[(size_t)Nn * Mm];   // (SC - off_i)*L2E
static __device__ __align__(16) __half g_HT[(size_t)Mm * Nn];
static __device__ float g_nx[Nn], g_ny[Mm], g_off[Nn];          // off in ln units
static __device__ float g_la[Nn], g_lb[Mm];                     // ln units
static __device__ float g_la2[Nn], g_lb2[Mm];                   // log2 units
static __device__ __align__(16) __half g_wah[Nn];               // wa2 (log2) fp16
static __device__ __align__(16) __half g_vbh[Mm];               // vb2 (log2) fp16
static __device__ float g_Lp[Nn];                               // prior row-LSE (phase A shift)
static __device__ float g_L2f[Nn], g_Lg2[Mm];                   // log2-LSE outputs
static __device__ float g_nybar;

__device__ __forceinline__ __half2 hexp2_(__half2 x) {
    uint32_t xi = *reinterpret_cast<uint32_t*>(&x), yi;
    asm("ex2.approx.f16x2 %0, %1;" : "=r"(yi) : "r"(xi));
    return *reinterpret_cast<__half2*>(&yi);
}
__device__ __forceinline__ uint32_t packh2(float a, float b) {
    __half2 h = __floats2half2_rn(a, b);
    return *reinterpret_cast<uint32_t*>(&h);
}
__device__ __forceinline__ void ldsm_x4(uint32_t (&r)[4], uint32_t a) {
    asm volatile("ldmatrix.sync.aligned.m8n8.x4.shared.b16 {%0,%1,%2,%3}, [%4];"
        : "=r"(r[0]), "=r"(r[1]), "=r"(r[2]), "=r"(r[3]) : "r"(a));
}
__device__ __forceinline__ void ldsm_x2(uint32_t (&r)[2], uint32_t a) {
    asm volatile("ldmatrix.sync.aligned.m8n8.x2.shared.b16 {%0,%1}, [%2];"
        : "=r"(r[0]), "=r"(r[1]) : "r"(a));
}

__global__ void prep_kernel(const float* __restrict__ h, const float* __restrict__ hi) {
    int i = blockIdx.x * blockDim.x + threadIdx.x;
    if (i < Nn) { float l = logf(h[i]); g_la[i] = l; g_la2[i] = l * L2E; }
    if (i < Mm) {
        float l = logf(hi[i]);
        g_lb[i] = l; g_lb2[i] = l * L2E;
        g_vbh[i] = __float2half(l * L2E);
    }
}

// fp32 -> fp16 conversion of d, si, W (float4 granularity)
#define D4 (Nn * Dd / 4)
#define S4 (Mm * Dd / 4)
#define W4 (Dd * Dd / 4)
__global__ void conv_kernel(const float* __restrict__ dp, const float* __restrict__ sip,
                            const float* __restrict__ Wp) {
    int idx = blockIdx.x * blockDim.x + threadIdx.x;
    const float* src; __half* dst; int q;
    if (idx < D4) { src = dp; dst = g_dh; q = idx; }
    else if (idx < D4 + S4) { src = sip; dst = g_sih; q = idx - D4; }
    else if (idx < D4 + S4 + W4) { src = Wp; dst = g_Wh; q = idx - D4 - S4; }
    else return;
    float4 v = ((const float4*)src)[q];
    ((uint2*)dst)[q] = make_uint2(packh2(v.x, v.y), packh2(v.z, v.w));
}

// ============ fp16 GEMM, tile 128x128, 256 thr, 2 blocks/SM, ldmatrix frags ============
// EPI=0: merged projections. EPI=1: gram + cost epilogue -> g_H and g_HT.
template <int EPI>
__global__ void __launch_bounds__(256, 2) h_gemm() {
    __shared__ union SU {
        struct { __half As[128][72]; __half Bs[128][72]; } k;
        __half tile[128][136];
    } su;
    const int t = threadIdx.x, lane = t & 31, wid = t >> 5;
    const int wm = wid & 1, wn = wid >> 1;
    const int tg = lane & 3, gp = lane >> 2;

    const __half *A, *B;
    __half* Cout = nullptr;
    int bi, bj;
    if (EPI == 0) {
        const int by = blockIdx.y;
        if (by < Nn / 128) { A = g_dh; Cout = g_Xh; bi = by * 128; }
        else { A = g_sih; Cout = g_Yh; bi = (by - Nn / 128) * 128; }
        B = g_Wh; bj = blockIdx.x * 128;
    } else {
        A = g_Xh; B = g_Yh;
        bi = blockIdx.y * 128; bj = blockIdx.x * 128;
    }

    const int ar = t >> 1, side = (t & 1) * 32;
    float acc[4][4][4] = {};
    const uint4* Ap = (const uint4*)(A + (size_t)(bi + ar) * Dd + side);
    const uint4* Bp = (const uint4*)(B + (size_t)(bj + ar) * Dd + side);
    uint4 pa[4], pb[4];
    #pragma unroll
    for (int q = 0; q < 4; q++) { pa[q] = Ap[q]; pb[q] = Bp[q]; }

    // ldmatrix lane address bases
    const int arow = lane & 15, acolh = (lane >> 4) << 3;       // A: m16 x k16 region
    const int brow = lane & 7,  bcolh = ((lane >> 3) & 1) << 3; // B: n8 x k16 region
    uint32_t aBase[4], bBase[4];
    #pragma unroll
    for (int im = 0; im < 4; im++)
        aBase[im] = (uint32_t)__cvta_generic_to_shared(&su.k.As[wm * 64 + im * 16 + arow][acolh]);
    #pragma unroll
    for (int jn = 0; jn < 4; jn++)
        bBase[jn] = (uint32_t)__cvta_generic_to_shared(&su.k.Bs[wn * 32 + jn * 8 + brow][bcolh]);

    for (int ch = 0; ch < 12; ch++) {
        #pragma unroll
        for (int q = 0; q < 4; q++) {
            *(uint4*)&su.k.As[ar][side + 8 * q] = pa[q];
            *(uint4*)&su.k.Bs[ar][side + 8 * q] = pb[q];
        }
        __syncthreads();
        if (ch < 11) {
            const int o = (ch + 1) * 8;
            #pragma unroll
            for (int q = 0; q < 4; q++) { pa[q] = Ap[o + q]; pb[q] = Bp[o + q]; }
        }
        #pragma unroll
        for (int kk = 0; kk < 4; kk++) {
            const uint32_t koff = (uint32_t)(kk * 32);   // 16 halves = 32 bytes
            uint32_t ua[4][4], ub[4][2];
            #pragma unroll
            for (int im = 0; im < 4; im++) ldsm_x4(ua[im], aBase[im] + koff);
            #pragma unroll
            for (int jn = 0; jn < 4; jn++) ldsm_x2(ub[jn], bBase[jn] + koff);
            #pragma unroll
            for (int im = 0; im < 4; im++)
                #pragma unroll
                for (int jn = 0; jn < 4; jn++)
                    asm volatile(
                        "mma.sync.aligned.m16n8k16.row.col.f32.f16.f16.f32 "
                        "{%0,%1,%2,%3}, {%4,%5,%6,%7}, {%8,%9}, {%0,%1,%2,%3};"
                        : "+f"(acc[im][jn][0]), "+f"(acc[im][jn][1]),
                          "+f"(acc[im][jn][2]), "+f"(acc[im][jn][3])
                        : "r"(ua[im][0]), "r"(ua[im][1]), "r"(ua[im][2]), "r"(ua[im][3]),
                          "r"(ub[jn][0]), "r"(ub[jn][1]));
        }
        __syncthreads();
    }

    if (EPI == 0) {
        #pragma unroll
        for (int im = 0; im < 4; im++) {
            const int r0 = bi + wm * 64 + im * 16 + gp;
            #pragma unroll
            for (int jn = 0; jn < 4; jn++) {
                const int cb = bj + wn * 32 + jn * 8 + 2 * tg;
                *(uint32_t*)&Cout[(size_t)r0 * Dd + cb] = packh2(acc[im][jn][0], acc[im][jn][1]);
                *(uint32_t*)&Cout[(size_t)(r0 + 8) * Dd + cb] = packh2(acc[im][jn][2], acc[im][jn][3]);
            }
        }
    } else {
        const float nyb = g_nybar;
        __half2 hv[4][4][2];
        #pragma unroll
        for (int im = 0; im < 4; im++) {
            const int rl = wm * 64 + im * 16 + gp;
            const float nx0 = g_nx[bi + rl], nx1 = g_nx[bi + rl + 8];
            const float o0 = SCL * (nx0 + nyb), o1 = SCL * (nx1 + nyb);
            #pragma unroll
            for (int jn = 0; jn < 4; jn++) {
                const int cl = wn * 32 + jn * 8 + 2 * tg;
                const float ny0 = g_ny[bj + cl], ny1 = g_ny[bj + cl + 1];
                float v00 = SCL * fmaxf(nx0 + ny0 - acc[im][jn][0], 0.f) - o0;
                float v01 = SCL * fmaxf(nx0 + ny1 - acc[im][jn][1], 0.f) - o0;
                float v10 = SCL * fmaxf(nx1 + ny0 - acc[im][jn][2], 0.f) - o1;
                float v11 = SCL * fmaxf(nx1 + ny1 - acc[im][jn][3], 0.f) - o1;
                hv[im][jn][0] = __floats2half2_rn(v00, v01);
                hv[im][jn][1] = __floats2half2_rn(v10, v11);
                *(__half2*)(g_H + (size_t)(bi + rl) * Mm + bj + cl) = hv[im][jn][0];
                *(__half2*)(g_H + (size_t)(bi + rl + 8) * Mm + bj + cl) = hv[im][jn][1];
            }
        }
        __syncthreads();
        #pragma unroll
        for (int im = 0; im < 4; im++) {
            const int rl = wm * 64 + im * 16 + gp;
            #pragma unroll
            for (int jn = 0; jn < 4; jn++) {
                const int cl = wn * 32 + jn * 8 + 2 * tg;
                su.tile[cl][rl]         = __low2half(hv[im][jn][0]);
                su.tile[cl + 1][rl]     = __high2half(hv[im][jn][0]);
                su.tile[cl][rl + 8]     = __low2half(hv[im][jn][1]);
                su.tile[cl + 1][rl + 8] = __high2half(hv[im][jn][1]);
            }
        }
        __syncthreads();
        const int c = t >> 1, rseg = (t & 1) * 64;
        const uint4* src = (const uint4*)&su.tile[c][rseg];
        uint4* dst = (uint4*)(g_HT + (size_t)(bj + c) * Nn + bi + rseg);
        #pragma unroll
        for (int q = 0; q < 8; q++) dst[q] = src[q];
    }
}

__global__ void __launch_bounds__(256) rownorm2() {
    const int gwarp = blockIdx.x * 8 + (threadIdx.x >> 5);
    const int lane = threadIdx.x & 31;
    const __half* X;
    float* outn;
    int row;
    if (gwarp < Nn) { X = g_Xh; outn = g_nx; row = gwarp; }
    else if (gwarp < Nn + Mm) { X = g_Yh; outn = g_ny; row = gwarp - Nn; }
    else return;
    const uint4* xr = (const uint4*)(X + (size_t)row * Dd);
    float s = 0.f;
    #pragma unroll
    for (int k = 0; k < 3; k++) {
        uint4 u = xr[lane + 32 * k];
        const __half2* hp = (const __half2*)&u;
        #pragma unroll
        for (int c = 0; c < 4; c++) {
            float2 f = __half22float2(hp[c]);
            s = fmaf(f.x, f.x, s); s = fmaf(f.y, f.y, s);
        }
    }
    #pragma unroll
    for (int o = 16; o > 0; o >>= 1) s += __shfl_xor_sync(0xffffffffu, s, o);
    if (lane == 0) outn[row] = 0.5f * s;
}

// single block: nybar reduction then off vector (fused)
__global__ void __launch_bounds__(1024) nybar_off_kernel() {
    const int t = threadIdx.x;
    float s = 0.f;
    for (int j = t; j < Mm; j += 1024) s += g_ny[j];
    __shared__ float sd[1024];
    sd[t] = s; __syncthreads();
    for (int o = 512; o > 0; o >>= 1) { if (t < o) sd[t] += sd[t + o]; __syncthreads(); }
    const float nyb = sd[0] / (float)Mm;
    if (t == 0) g_nybar = nyb;
    for (int i = t; i < Nn; i += 1024) g_off[i] = 400.f * (g_nx[i] + nyb);
}

// ===== phase A warmup: two-pass softmin over H rows (1 warp/row); stores L to g_Lp =====
__global__ void __launch_bounds__(256) softminA_w() {
    const int t = threadIdx.x, lane = t & 31, wid = t >> 5;
    const int row = blockIdx.x * 8 + wid;
    const uint4* Hr = (const uint4*)(g_H + (size_t)row * Mm);
    const uint4* Vr = (const uint4*)g_vbh;

    __half2 a[8][4];
    __half2 m2 = __float2half2_rn(-60000.f);
    #pragma unroll
    for (int q = 0; q < 8; q++) {
        const int idx = q * 32 + lane;
        uint4 hu = Hr[idx];
        uint4 vu = __ldg(&Vr[idx]);
        const __half2* hp = (const __half2*)&hu;
        const __half2* vp = (const __half2*)&vu;
        #pragma unroll
        for (int c = 0; c < 4; c++) {
            a[q][c] = __hsub2(vp[c], hp[c]);
            m2 = __hmax2(m2, a[q][c]);
        }
    }
    float m = fmaxf(__half2float(__low2half(m2)), __half2float(__high2half(m2)));
    #pragma unroll
    for (int o = 16; o > 0; o >>= 1) m = fmaxf(m, __shfl_xor_sync(0xffffffffu, m, o));
    const __half2 mh = __float2half2_rn(m);

    float s0 = 0.f, s1 = 0.f;
    #pragma unroll
    for (int q = 0; q < 8; q++) {
        __half2 p = __float2half2_rn(0.f);
        #pragma unroll
        for (int c = 0; c < 4; c++) p = __hadd2(p, hexp2_(__hsub2(a[q][c], mh)));
        float pf = __half2float(__hadd(__low2half(p), __high2half(p)));
        if (q & 1) s1 += pf; else s0 += pf;
    }
    float s = s0 + s1;
    #pragma unroll
    for (int o = 16; o > 0; o >>= 1) s += __shfl_xor_sync(0xffffffffu, s, o);
    if (lane == 0) {
        float L = m + __log2f(s);
        g_Lp[row] = L;
        g_wah[row] = __float2half(g_la2[row] - L);
    }
}

// ===== phase A steady: ONE-PASS shifted by prior L (1 warp/row, 8 rows/block) =====
template <int FINAL>
__global__ void __launch_bounds__(256) softminA1() {
    const int t = threadIdx.x, lane = t & 31, wid = t >> 5;
    const int row = blockIdx.x * 8 + wid;
    const uint4* Hr = (const uint4*)(g_H + (size_t)row * Mm);
    const uint4* Vr = (const uint4*)g_vbh;
    const float Lp = g_Lp[row];
    const __half2 Lp2 = __float2half2_rn(Lp);

    float s0 = 0.f, s1 = 0.f;
    #pragma unroll
    for (int q = 0; q < 8; q++) {
        const int idx = q * 32 + lane;
        uint4 hu = Hr[idx];
        uint4 vu = __ldg(&Vr[idx]);
        const __half2* hp = (const __half2*)&hu;
        const __half2* vp = (const __half2*)&vu;
        __half2 p = __float2half2_rn(0.f);
        #pragma unroll
        for (int c = 0; c < 4; c++)
            p = __hadd2(p, hexp2_(__hsub2(__hsub2(vp[c], hp[c]), Lp2)));
        float pf = __half2float(__hadd(__low2half(p), __high2half(p)));
        if (q & 1) s1 += pf; else s0 += pf;
    }
    float s = s0 + s1;
    #pragma unroll
    for (int o = 16; o > 0; o >>= 1) s += __shfl_xor_sync(0xffffffffu, s, o);
    if (lane == 0) {
        float L = Lp + __log2f(s);
        g_Lp[row] = L;
        if (FINAL) g_L2f[row] = L;
        else g_wah[row] = __float2half(g_la2[row] - L);
    }
}

// ===== phase B warmup: two-pass over HT rows (4 warps/row, 2 rows/block) =====
__global__ void __launch_bounds__(256) softminB_w() {
    __shared__ float sM[2][4], sS[2][4];
    const int t = threadIdx.x, lane = t & 31, wid = t >> 5;
    const int rloc = wid >> 2, quarter = wid & 3;
    const int row = blockIdx.x * 2 + rloc;
    const uint4* Hr = (const uint4*)(g_HT + (size_t)row * Nn);
    const uint4* Vr = (const uint4*)g_wah;

    __half2 a[8][4];
    __half2 m2 = __float2half2_rn(-60000.f);
    #pragma unroll
    for (int q = 0; q < 8; q++) {
        const int idx = quarter * 256 + q * 32 + lane;
        uint4 hu = Hr[idx];
        uint4 vu = __ldg(&Vr[idx]);
        const __half2* hp = (const __half2*)&hu;
        const __half2* vp = (const __half2*)&vu;
        #pragma unroll
        for (int c = 0; c < 4; c++) {
            a[q][c] = __hsub2(vp[c], hp[c]);
            m2 = __hmax2(m2, a[q][c]);
        }
    }
    float m = fmaxf(__half2float(__low2half(m2)), __half2float(__high2half(m2)));
    #pragma unroll
    for (int o = 16; o > 0; o >>= 1) m = fmaxf(m, __shfl_xor_sync(0xffffffffu, m, o));
    const __half2 mh = __float2half2_rn(m);

    float s0 = 0.f, s1 = 0.f;
    #pragma unroll
    for (int q = 0; q < 8; q++) {
        __half2 p = __float2half2_rn(0.f);
        #pragma unroll
        for (int c = 0; c < 4; c++) p = __hadd2(p, hexp2_(__hsub2(a[q][c], mh)));
        float pf = __half2float(__hadd(__low2half(p), __high2half(p)));
        if (q & 1) s1 += pf; else s0 += pf;
    }
    float s = s0 + s1;
    #pragma unroll
    for (int o = 16; o > 0; o >>= 1) s += __shfl_xor_sync(0xffffffffu, s, o);

    if (lane == 0) { sM[rloc][quarter] = m; sS[rloc][quarter] = s; }
    __syncthreads();
    if (t < 2) {
        float M2 = sM[t][0];
        #pragma unroll
        for (int w = 1; w < 4; w++) M2 = fmaxf(M2, sM[t][w]);
        float S2 = 0.f;
        #pragma unroll
        for (int w = 0; w < 4; w++) S2 += sS[t][w] * exp2f(sM[t][w] - M2);
        float L = M2 + __log2f(S2);
        const int r = blockIdx.x * 2 + t;
        g_vbh[r] = __float2half(g_lb2[r] - L);
        g_Lg2[r] = L;
    }
}

// ===== phase B steady: ONE-PASS shifted by prior Lg2 (4 warps/row, 2 rows/block) =====
__global__ void __launch_bounds__(256) softminB1() {
    __shared__ float sS[2][4];
    const int t = threadIdx.x, lane = t & 31, wid = t >> 5;
    const int rloc = wid >> 2, quarter = wid & 3;
    const int row = blockIdx.x * 2 + rloc;
    const uint4* Hr = (const uint4*)(g_HT + (size_t)row * Nn);
    const uint4* Vr = (const uint4*)g_wah;
    const __half2 Lp2 = __float2half2_rn(g_Lg2[row]);

    float s0 = 0.f, s1 = 0.f;
    #pragma unroll
    for (int q = 0; q < 8; q++) {
        const int idx = quarter * 256 + q * 32 + lane;
        uint4 hu = Hr[idx];
        uint4 vu = __ldg(&Vr[idx]);
        const __half2* hp = (const __half2*)&hu;
        const __half2* vp = (const __half2*)&vu;
        __half2 p = __float2half2_rn(0.f);
        #pragma unroll
        for (int c = 0; c < 4; c++)
            p = __hadd2(p, hexp2_(__hsub2(__hsub2(vp[c], hp[c]), Lp2)));
        float pf = __half2float(__hadd(__low2half(p), __high2half(p)));
        if (q & 1) s1 += pf; else s0 += pf;
    }
    float s = s0 + s1;
    #pragma unroll
    for (int o = 16; o > 0; o >>= 1) s += __shfl_xor_sync(0xffffffffu, s, o);

    if (lane == 0) sS[rloc][quarter] = s;
    __syncthreads();
    if (t < 2) {
        const int r = blockIdx.x * 2 + t;
        float S2 = sS[t][0] + sS[t][1] + sS[t][2] + sS[t][3];
        float L = g_Lg2[r] + __log2f(S2);
        g_vbh[r] = __float2half(g_lb2[r] - L);
        g_Lg2[r] = L;
    }
}

__global__ void final_kernel(const float* __restrict__ h, const float* __restrict__ hi,
                             float* __restrict__ out) {
    const int t = threadIdx.x;
    double acc = 0.0;
    for (int i = t; i < Nn; i += 256)
        acc += (double)h[i] * (LN2 * (double)g_L2f[i] - (double)g_off[i] - 0.5 * (double)g_la[i]);
    for (int j = t; j < Mm; j += 256)
        acc += (double)hi[j] * (LN2 * (double)g_Lg2[j] - 0.5 * (double)g_lb[j]);
    __shared__ double sd[256];
    sd[t] = acc; __syncthreads();
    for (int o = 128; o > 0; o >>= 1) { if (t < o) sd[t] += sd[t + o]; __syncthreads(); }
    if (t == 0) out[0] = (float)exp(EPS_D * sd[0]);
}

extern "C" void kernel_launch(void* const* d_in, const int* in_sizes, int n_in,
                              void* d_out, int out_size) {
    const float *dp = nullptr, *sip = nullptr, *hp = nullptr, *hip = nullptr, *Wp = nullptr;
    for (int i = 0; i < n_in; i++) {
        switch (in_sizes[i]) {
            case Nn * Dd: dp  = (const float*)d_in[i]; break;
            case Mm * Dd: sip = (const float*)d_in[i]; break;
            case Nn:      hp  = (const float*)d_in[i]; break;
            case Mm:      hip = (const float*)d_in[i]; break;
            case Dd * Dd: Wp  = (const float*)d_in[i]; break;
        }
    }
    if (!dp)  dp  = (const float*)d_in[0];
    if (!sip) sip = (const float*)d_in[1];
    if (!hp)  hp  = (const float*)d_in[2];
    if (!hip) hip = (const float*)d_in[3];
    if (!Wp)  Wp  = (const float*)d_in[4];

    prep_kernel<<<(Nn + 255) / 256, 256>>>(hp, hip);
    conv_kernel<<<(D4 + S4 + W4 + 255) / 256, 256>>>(dp, sip, Wp);
    h_gemm<0><<<dim3(Dd / 128, (Nn + Mm) / 128), 256>>>();   // merged projections
    rownorm2<<<(Nn + Mm) / 8, 256>>>();
    nybar_off_kernel<<<1, 1024>>>();
    h_gemm<1><<<dim3(Mm / 128, Nn / 128), 256>>>();          // gram + cost epilogue

    for (int it = 0; it < 4; it++) {
        softminA_w<<<Nn / 8, 256>>>();
        softminB_w<<<Mm / 2, 256>>>();
    }
    for (int it = 4; it < 36; it++) {
        softminA1<0><<<Nn / 8, 256>>>();
        softminB1<<<Mm / 2, 256>>>();
    }
    softminA1<1><<<Nn / 8, 256>>>();

    final_kernel<<<1, 256>>>(hp, hip, (float*)d_out);
}